// round 16
// baseline (speedup 1.0000x reference)
#include <cuda_runtime.h>
#include <cuda_fp16.h>
#include <math.h>
#include <stdint.h>

// ---------------------------------------------------------------------------
// SALAD pipeline. Round 16 = R11 (421 us, best) with finalize fused into agg
// via a per-batch arrival counter (last of the 4 l-quad blocks finalizes).
// All GEMM kernels byte-identical to R11 (converged local optimum).
// ---------------------------------------------------------------------------

#define B_SZ 32
#define C_SZ 1536
#define HW   1024
#define HID  512
#define L_D  128
#define M_CL 64
#define G_D  256
#define EPSV 1e-12f

__device__ __align__(256) __half g_H[(size_t)B_SZ * 1024 * HW];      // H [b][k][n]
__device__ __align__(256) float g_F[(size_t)B_SZ * L_D * HW];
__device__ __align__(256) float g_Z[(size_t)B_SZ * (M_CL + 1) * HW];
__device__ __align__(256) float g_AGG[(size_t)B_SZ * L_D * M_CL];
__device__ __align__(256) float g_TK[(size_t)B_SZ * G_D];
__device__ int g_cnt[B_SZ];                                          // zero-init

__device__ __align__(256) __half g_X[(size_t)B_SZ * C_SZ * HW];  // x [b][c][n]
__device__ __align__(256) __half g_W1[(size_t)1024 * C_SZ];      // [cf_w1; sc_w1]
__device__ __align__(256) __half g_W2[(size_t)256 * HID];        // [cf_w2; sc_w2; 0]
__device__ __align__(256) float g_B1c[1024];
__device__ __align__(256) float g_B2c[256];

// ---------------------------------------------------------------------------
__device__ __forceinline__ uint32_t smem_u32(const void* p) {
    uint32_t a;
    asm("{ .reg .u64 t; cvta.to.shared.u64 t, %1; cvt.u32.u64 %0, t; }"
        : "=r"(a) : "l"(p));
    return a;
}

__device__ __forceinline__ void cp16(uint32_t saddr, const void* gaddr) {
    asm volatile("cp.async.cg.shared.global [%0], [%1], 16;"
                 :: "r"(saddr), "l"(gaddr) : "memory");
}

#define LDSM_X4(r0, r1, r2, r3, addr) \
    asm volatile("ldmatrix.sync.aligned.m8n8.x4.shared.b16 {%0,%1,%2,%3}, [%4];" \
                 : "=r"(r0), "=r"(r1), "=r"(r2), "=r"(r3) : "r"(addr))

#define LDSM_X4_T(r0, r1, r2, r3, addr) \
    asm volatile("ldmatrix.sync.aligned.m8n8.x4.trans.shared.b16 {%0,%1,%2,%3}, [%4];" \
                 : "=r"(r0), "=r"(r1), "=r"(r2), "=r"(r3) : "r"(addr))

#define MMA_F16(d, a, b0, b1) \
    asm volatile("mma.sync.aligned.m16n8k16.row.col.f32.f16.f16.f32 " \
                 "{%0,%1,%2,%3}, {%4,%5,%6,%7}, {%8,%9}, {%0,%1,%2,%3};" \
                 : "+f"((d)[0]), "+f"((d)[1]), "+f"((d)[2]), "+f"((d)[3]) \
                 : "r"((a)[0]), "r"((a)[1]), "r"((a)[2]), "r"((a)[3]), \
                   "r"(b0), "r"(b1))

// ---------------------------------------------------------------------------
// Merged weight conversion
// ---------------------------------------------------------------------------
__global__ __launch_bounds__(256)
void convert_all_kernel(const float* __restrict__ cf_w1, const float* __restrict__ sc_w1,
                        const float* __restrict__ cf_b1, const float* __restrict__ sc_b1,
                        const float* __restrict__ cf_w2, const float* __restrict__ sc_w2,
                        const float* __restrict__ cf_b2, const float* __restrict__ sc_b2)
{
    size_t idx = (size_t)blockIdx.x * 256 + threadIdx.x;
    const size_t totalW1 = (size_t)1024 * C_SZ;
    if (idx < totalW1) {
        float v = (idx < (size_t)HID * C_SZ) ? cf_w1[idx]
                                             : sc_w1[idx - (size_t)HID * C_SZ];
        g_W1[idx] = __float2half_rn(v);
    }
    if (idx < (size_t)256 * HID) {
        size_t row = idx / HID;
        float v = 0.f;
        if (row < L_D)      v = cf_w2[idx];
        else if (row < 192) v = sc_w2[idx - (size_t)L_D * HID];
        g_W2[idx] = __float2half_rn(v);
    }
    if (idx < 1024)
        g_B1c[idx] = (idx < HID) ? cf_b1[idx] : sc_b1[idx - HID];
    if (idx < 256)
        g_B2c[idx] = (idx < L_D) ? cf_b2[idx]
                   : (idx < 192) ? sc_b2[idx - L_D] : 0.f;
}

__global__ __launch_bounds__(256)
void convert_x_kernel(const float4* __restrict__ x)
{
    const size_t i = (size_t)blockIdx.x * 256 + threadIdx.x;
    float4 a = x[2 * i];
    float4 b = x[2 * i + 1];
    __half2 h0 = __floats2half2_rn(a.x, a.y);
    __half2 h1 = __floats2half2_rn(a.z, a.w);
    __half2 h2 = __floats2half2_rn(b.x, b.y);
    __half2 h3 = __floats2half2_rn(b.z, b.w);
    uint4 o;
    o.x = *reinterpret_cast<uint32_t*>(&h0);
    o.y = *reinterpret_cast<uint32_t*>(&h1);
    o.z = *reinterpret_cast<uint32_t*>(&h2);
    o.w = *reinterpret_cast<uint32_t*>(&h3);
    reinterpret_cast<uint4*>(g_X)[i] = o;
}

// ---------------------------------------------------------------------------
// GEMM1 (fp16 HMMA): H[b] = relu(W1 @ X[b] + b1) -> fp16
//   CTA 128x128, KC=64, 3-stage cp.async, 2 CTAs/SM. (R11-proven, frozen)
// ---------------------------------------------------------------------------
#define MT 128
#define NT 128
#define KC 64
#define NK1 (C_SZ / KC)               // 24
#define NK2 (HID / KC)                // 8
#define OFF_A 0
#define OFF_B (16 * 1024)
#define STAGE_BYTES (32 * 1024)
#define GEMM_SMEM (3 * STAGE_BYTES)   // 96 KB

__global__ __launch_bounds__(256, 2)
void mma_gemm1_kernel(const __half* __restrict__ W1, const __half* __restrict__ X,
                      const float* __restrict__ bias, __half* __restrict__ H)
{
    extern __shared__ char dsmem[];
    const uint32_t smem_base = smem_u32(dsmem);

    const int tid = threadIdx.x;
    const int b  = blockIdx.z;
    const int n0 = blockIdx.x * NT;
    const int m0 = blockIdx.y * MT;

    const __half* Ag = W1 + (size_t)m0 * C_SZ;
    const __half* Bg = X + (size_t)b * C_SZ * HW + n0;

    const int lane = tid & 31, warp = tid >> 5;
    const int wm = warp >> 2, wn = warp & 3;

    const uint32_t lx = (uint32_t)(lane & 7);
    const uint32_t aG = (uint32_t)(lane >> 4);
    const uint32_t aRowOff = (uint32_t)(wm * 64 + (lane & 15)) * 128u;
    const uint32_t bRowOff = (uint32_t)(lane & 15) * 256u;
    const uint32_t bGbase = (uint32_t)(wn * 4) + (uint32_t)(lane >> 4);

    float acc[4][4][4];
    #pragma unroll
    for (int i = 0; i < 4; ++i)
        #pragma unroll
        for (int j = 0; j < 4; ++j)
            #pragma unroll
            for (int q = 0; q < 4; ++q) acc[i][j][q] = 0.f;

    auto load_chunk = [&](int c) {
        const uint32_t sb = smem_base + (uint32_t)(c % 3) * STAGE_BYTES;
        const size_t kk = (size_t)c * KC;
        #pragma unroll
        for (int i = 0; i < 4; ++i) {
            int idx = tid + 256 * i;
            int r = idx >> 3, g = idx & 7;
            uint32_t so = (uint32_t)r * 128u + (uint32_t)((g ^ (r & 7)) << 4);
            cp16(sb + OFF_A + so, (const char*)(Ag + (size_t)r * C_SZ + kk) + g * 16);
        }
        #pragma unroll
        for (int i = 0; i < 4; ++i) {
            int idx = tid + 256 * i;
            int r = idx >> 4, g = idx & 15;
            uint32_t so = (uint32_t)r * 256u + (uint32_t)((g ^ (r & 7)) << 4);
            cp16(sb + OFF_B + so, (const char*)(Bg + (kk + r) * HW) + g * 16);
        }
        asm volatile("cp.async.commit_group;" ::: "memory");
    };

    load_chunk(0);
    load_chunk(1);

    for (int c = 0; c < NK1; ++c) {
        if (c + 2 < NK1) {
            load_chunk(c + 2);
            asm volatile("cp.async.wait_group 2;" ::: "memory");
        } else if (c + 1 < NK1) {
            asm volatile("cp.async.wait_group 1;" ::: "memory");
        } else {
            asm volatile("cp.async.wait_group 0;" ::: "memory");
        }
        __syncthreads();

        const uint32_t sb = smem_base + (uint32_t)(c % 3) * STAGE_BYTES;

        #pragma unroll
        for (int ks = 0; ks < 4; ++ks) {
            const uint32_t gA = ((uint32_t)(ks * 2) + aG) ^ lx;
            const uint32_t bRow = (uint32_t)(ks * 16) * 256u + bRowOff;

            uint32_t ah[16], bh[8];
            #pragma unroll
            for (int ma = 0; ma < 4; ++ma) {
                uint32_t ad = sb + OFF_A + aRowOff + (uint32_t)(ma * 16 * 128) + (gA << 4);
                LDSM_X4(ah[4*ma+0], ah[4*ma+1], ah[4*ma+2], ah[4*ma+3], ad);
            }
            #pragma unroll
            for (int nb = 0; nb < 2; ++nb) {
                uint32_t gB = (bGbase + (uint32_t)(nb * 2)) ^ lx;
                uint32_t bd = sb + OFF_B + bRow + (gB << 4);
                LDSM_X4_T(bh[4*nb+0], bh[4*nb+1], bh[4*nb+2], bh[4*nb+3], bd);
            }
            #pragma unroll
            for (int ma = 0; ma < 4; ++ma)
                #pragma unroll
                for (int na = 0; na < 4; ++na)
                    MMA_F16(acc[ma][na], &ah[4*ma], bh[2*na], bh[2*na+1]);
        }
        __syncthreads();
    }

    const int g  = lane >> 2;
    const int tc = lane & 3;
    #pragma unroll
    for (int ma = 0; ma < 4; ++ma) {
        const int r0 = m0 + wm * 64 + ma * 16 + g;
        const int r1 = r0 + 8;
        const float bb0 = bias[r0];
        const float bb1 = bias[r1];
        const size_t base0 = ((size_t)b * 1024 + r0) * HW + n0 + wn * 32 + tc * 2;
        const size_t base1 = ((size_t)b * 1024 + r1) * HW + n0 + wn * 32 + tc * 2;
        #pragma unroll
        for (int na = 0; na < 4; ++na) {
            float v00 = fmaxf(acc[ma][na][0] + bb0, 0.f);
            float v01 = fmaxf(acc[ma][na][1] + bb0, 0.f);
            float v10 = fmaxf(acc[ma][na][2] + bb1, 0.f);
            float v11 = fmaxf(acc[ma][na][3] + bb1, 0.f);
            *reinterpret_cast<__half2*>(H + base0 + na * 8) = __floats2half2_rn(v00, v01);
            *reinterpret_cast<__half2*>(H + base1 + na * 8) = __floats2half2_rn(v10, v11);
        }
    }
}

// ---------------------------------------------------------------------------
// GEMM2 (fp16 HMMA, gemm1 clone): [F; Z] = W2p @ H + b2p  (R11-proven)
// ---------------------------------------------------------------------------
__global__ __launch_bounds__(256, 2)
void mma_gemm2_kernel(const __half* __restrict__ W2p, const __half* __restrict__ H,
                      const float* __restrict__ bias,
                      float* __restrict__ Fout, float* __restrict__ Zout)
{
    extern __shared__ char dsmem[];
    const uint32_t smem_base = smem_u32(dsmem);

    const int tid = threadIdx.x;
    const int b  = blockIdx.z;
    const int n0 = blockIdx.x * NT;
    const int m0 = blockIdx.y * MT;                // 0 or 128
    const int koff = (m0 == 128) ? 512 : 0;

    const __half* Ag = W2p + (size_t)m0 * HID;
    const __half* Bg = H + ((size_t)b * 1024 + koff) * HW + n0;

    const int lane = tid & 31, warp = tid >> 5;
    const int wm = warp >> 2, wn = warp & 3;

    const uint32_t lx = (uint32_t)(lane & 7);
    const uint32_t aG = (uint32_t)(lane >> 4);
    const uint32_t aRowOff = (uint32_t)(wm * 64 + (lane & 15)) * 128u;
    const uint32_t bRowOff = (uint32_t)(lane & 15) * 256u;
    const uint32_t bGbase = (uint32_t)(wn * 4) + (uint32_t)(lane >> 4);

    float acc[4][4][4];
    #pragma unroll
    for (int i = 0; i < 4; ++i)
        #pragma unroll
        for (int j = 0; j < 4; ++j)
            #pragma unroll
            for (int q = 0; q < 4; ++q) acc[i][j][q] = 0.f;

    auto load_chunk = [&](int c) {
        const uint32_t sb = smem_base + (uint32_t)(c % 3) * STAGE_BYTES;
        const size_t kk = (size_t)c * KC;
        #pragma unroll
        for (int i = 0; i < 4; ++i) {
            int idx = tid + 256 * i;
            int r = idx >> 3, g = idx & 7;
            uint32_t so = (uint32_t)r * 128u + (uint32_t)((g ^ (r & 7)) << 4);
            cp16(sb + OFF_A + so, (const char*)(Ag + (size_t)r * HID + kk) + g * 16);
        }
        #pragma unroll
        for (int i = 0; i < 4; ++i) {
            int idx = tid + 256 * i;
            int r = idx >> 4, g = idx & 15;
            uint32_t so = (uint32_t)r * 256u + (uint32_t)((g ^ (r & 7)) << 4);
            cp16(sb + OFF_B + so, (const char*)(Bg + (kk + r) * HW) + g * 16);
        }
        asm volatile("cp.async.commit_group;" ::: "memory");
    };

    load_chunk(0);
    load_chunk(1);

    for (int c = 0; c < NK2; ++c) {
        if (c + 2 < NK2) {
            load_chunk(c + 2);
            asm volatile("cp.async.wait_group 2;" ::: "memory");
        } else if (c + 1 < NK2) {
            asm volatile("cp.async.wait_group 1;" ::: "memory");
        } else {
            asm volatile("cp.async.wait_group 0;" ::: "memory");
        }
        __syncthreads();

        const uint32_t sb = smem_base + (uint32_t)(c % 3) * STAGE_BYTES;

        #pragma unroll
        for (int ks = 0; ks < 4; ++ks) {
            const uint32_t gA = ((uint32_t)(ks * 2) + aG) ^ lx;
            const uint32_t bRow = (uint32_t)(ks * 16) * 256u + bRowOff;

            uint32_t ah[16], bh[8];
            #pragma unroll
            for (int ma = 0; ma < 4; ++ma) {
                uint32_t ad = sb + OFF_A + aRowOff + (uint32_t)(ma * 16 * 128) + (gA << 4);
                LDSM_X4(ah[4*ma+0], ah[4*ma+1], ah[4*ma+2], ah[4*ma+3], ad);
            }
            #pragma unroll
            for (int nb = 0; nb < 2; ++nb) {
                uint32_t gB = (bGbase + (uint32_t)(nb * 2)) ^ lx;
                uint32_t bd = sb + OFF_B + bRow + (gB << 4);
                LDSM_X4_T(bh[4*nb+0], bh[4*nb+1], bh[4*nb+2], bh[4*nb+3], bd);
            }
            #pragma unroll
            for (int ma = 0; ma < 4; ++ma)
                #pragma unroll
                for (int na = 0; na < 4; ++na)
                    MMA_F16(acc[ma][na], &ah[4*ma], bh[2*na], bh[2*na+1]);
        }
        __syncthreads();
    }

    const int g  = lane >> 2;
    const int tc = lane & 3;
    #pragma unroll
    for (int ma = 0; ma < 4; ++ma) {
        const int r0 = m0 + wm * 64 + ma * 16 + g;
        const int r1 = r0 + 8;
        const float bb0 = bias[r0];
        const float bb1 = bias[r1];
        float* p0 = nullptr;
        float* p1 = nullptr;
        if (r0 < L_D)      p0 = Fout + ((size_t)b * L_D + r0) * HW;
        else if (r0 < 192) p0 = Zout + ((size_t)b * (M_CL + 1) + (r0 - L_D)) * HW;
        if (r1 < L_D)      p1 = Fout + ((size_t)b * L_D + r1) * HW;
        else if (r1 < 192) p1 = Zout + ((size_t)b * (M_CL + 1) + (r1 - L_D)) * HW;
        const int coff = n0 + wn * 32 + tc * 2;
        #pragma unroll
        for (int na = 0; na < 4; ++na) {
            if (p0) {
                float2 v0;
                v0.x = acc[ma][na][0] + bb0;
                v0.y = acc[ma][na][1] + bb0;
                *reinterpret_cast<float2*>(p0 + coff + na * 8) = v0;
            }
            if (p1) {
                float2 v1;
                v1.x = acc[ma][na][2] + bb1;
                v1.y = acc[ma][na][3] + bb1;
                *reinterpret_cast<float2*>(p1 + coff + na * 8) = v1;
            }
        }
    }
}

// ---------------------------------------------------------------------------
// Fused token MLP
// ---------------------------------------------------------------------------
__global__ __launch_bounds__(256)
void token_kernel(const float* __restrict__ t,
                  const float* __restrict__ w1, const float* __restrict__ b1,
                  const float* __restrict__ w2, const float* __restrict__ b2)
{
    __shared__ float ts[C_SZ];
    __shared__ float hs[HID];
    const int b = blockIdx.x;
    for (int c = threadIdx.x; c < C_SZ; c += 256) ts[c] = t[(size_t)b * C_SZ + c];
    __syncthreads();
    const int wid = threadIdx.x >> 5, lane = threadIdx.x & 31;
    for (int o = wid; o < HID; o += 8) {
        const float* wr = w1 + (size_t)o * C_SZ;
        float s = 0.f;
        for (int c = lane; c < C_SZ; c += 32) s = fmaf(ts[c], wr[c], s);
        #pragma unroll
        for (int off = 16; off; off >>= 1) s += __shfl_xor_sync(0xFFFFFFFFu, s, off);
        if (lane == 0) hs[o] = fmaxf(s + b1[o], 0.f);
    }
    __syncthreads();
    for (int o = wid; o < G_D; o += 8) {
        const float* wr = w2 + (size_t)o * HID;
        float s = 0.f;
        for (int c = lane; c < HID; c += 32) s = fmaf(hs[c], wr[c], s);
        #pragma unroll
        for (int off = 16; off; off >>= 1) s += __shfl_xor_sync(0xFFFFFFFFu, s, off);
        if (lane == 0) g_TK[(size_t)b * G_D + o] = s + b2[o];
    }
}

// ---------------------------------------------------------------------------
// Sinkhorn, 512 threads (2 columns/thread), one block per batch.
// Overwrites Z rows 0..63 with P in place (R11 semantics).
// ---------------------------------------------------------------------------
__global__ __launch_bounds__(512)
void sinkhorn_kernel(const float* __restrict__ alpha_p)
{
    const int b = blockIdx.x;
    float* Zb = g_Z + (size_t)b * (M_CL + 1) * HW;

    __shared__ float u[M_CL + 1];
    __shared__ float wsum[M_CL + 1][17];

    const int j = threadIdx.x;
    const int lane = j & 31, warp = j >> 5;   // 16 warps
    const float alpha = *alpha_p;
    const float norm = -logf((float)(M_CL + HW));
    const float log_mu_last = logf((float)(HW - M_CL)) + norm;

    float v0 = 0.f, v1 = 0.f;

    for (int it = 0; it < 3; ++it) {
        #pragma unroll 4
        for (int i = 0; i <= M_CL; ++i) {
            float z0, z1;
            if (i < M_CL) {
                z0 = Zb[(size_t)i * HW + j] + v0;
                z1 = Zb[(size_t)i * HW + j + 512] + v1;
            } else {
                z0 = alpha + v0;
                z1 = alpha + v1;
            }
            float e = __expf(z0) + __expf(z1);
            #pragma unroll
            for (int off = 16; off; off >>= 1) e += __shfl_xor_sync(0xFFFFFFFFu, e, off);
            if (lane == 0) wsum[i][warp] = e;
        }
        __syncthreads();
        if (j <= M_CL) {
            float s = 0.f;
            #pragma unroll
            for (int w = 0; w < 16; ++w) s += wsum[j][w];
            u[j] = ((j < M_CL) ? norm : log_mu_last) - logf(s);
        }
        __syncthreads();

        float s0 = 0.f, s1 = 0.f;
        #pragma unroll 8
        for (int i = 0; i < M_CL; ++i) {
            s0 += __expf(Zb[(size_t)i * HW + j] + u[i]);
            s1 += __expf(Zb[(size_t)i * HW + j + 512] + u[i]);
        }
        s0 += __expf(alpha + u[M_CL]);
        s1 += __expf(alpha + u[M_CL]);
        v0 = norm - logf(s0);
        v1 = norm - logf(s1);
    }

    #pragma unroll 8
    for (int i = 0; i < M_CL; ++i) {
        Zb[(size_t)i * HW + j]       = __expf(Zb[(size_t)i * HW + j] + u[i] + v0 - norm);
        Zb[(size_t)i * HW + j + 512] = __expf(Zb[(size_t)i * HW + j + 512] + u[i] + v1 - norm);
    }
}

// ---------------------------------------------------------------------------
// agg + fused finalize. grid (4 l-quads, B), 256 threads.
// Each block writes its 32-l AGG slice; the LAST block per batch (arrival
// counter) performs the finalize for that batch. Deterministic output.
// ---------------------------------------------------------------------------
__global__ __launch_bounds__(256)
void agg_finalize_kernel(float* __restrict__ out)
{
    const int b = blockIdx.y;
    const int l0 = blockIdx.x * 32;
    const float* Fb = g_F + (size_t)b * L_D * HW + (size_t)l0 * HW;
    const float* Pb = g_Z + (size_t)b * (M_CL + 1) * HW;
    float*       Cb = g_AGG + (size_t)b * L_D * M_CL + (size_t)l0 * M_CL;

    __shared__ float Fs[32][36];
    __shared__ float Ps[32][68];
    __shared__ int   s_last;

    const int tid = threadIdx.x;
    const int tx = tid & 15, ty = tid >> 4;

    float acc[2][4];
    #pragma unroll
    for (int i = 0; i < 2; ++i)
        #pragma unroll
        for (int j = 0; j < 4; ++j) acc[i][j] = 0.f;

    for (int n0 = 0; n0 < HW; n0 += 32) {
        {
            int l = tid >> 3, kq = (tid & 7) << 2;
            float4 fv = *reinterpret_cast<const float4*>(&Fb[(size_t)l * HW + n0 + kq]);
            Fs[kq + 0][l] = fv.x; Fs[kq + 1][l] = fv.y;
            Fs[kq + 2][l] = fv.z; Fs[kq + 3][l] = fv.w;
        }
        #pragma unroll
        for (int r = 0; r < 2; ++r) {
            int id = tid + 256 * r;
            int m = id >> 3, kq = (id & 7) << 2;
            float4 pv = *reinterpret_cast<const float4*>(&Pb[(size_t)m * HW + n0 + kq]);
            Ps[kq + 0][m] = pv.x; Ps[kq + 1][m] = pv.y;
            Ps[kq + 2][m] = pv.z; Ps[kq + 3][m] = pv.w;
        }
        __syncthreads();

        #pragma unroll
        for (int k = 0; k < 32; ++k) {
            float rl[2], rm[4];
            #pragma unroll
            for (int i = 0; i < 2; ++i) rl[i] = Fs[k][ty * 2 + i];
            #pragma unroll
            for (int j = 0; j < 4; ++j) rm[j] = Ps[k][tx * 4 + j];
            #pragma unroll
            for (int i = 0; i < 2; ++i)
                #pragma unroll
                for (int j = 0; j < 4; ++j)
                    acc[i][j] = fmaf(rl[i], rm[j], acc[i][j]);
        }
        __syncthreads();
    }

    #pragma unroll
    for (int i = 0; i < 2; ++i)
        #pragma unroll
        for (int j = 0; j < 4; ++j)
            Cb[(size_t)(ty * 2 + i) * M_CL + tx * 4 + j] = acc[i][j];

    // arrival counter: last of the 4 blocks for this batch finalizes
    __threadfence();
    __syncthreads();
    if (tid == 0) {
        int old = atomicAdd(&g_cnt[b], 1);
        s_last = (old == 3) ? 1 : 0;
    }
    __syncthreads();
    if (!s_last) return;

    // ---- finalize for batch b (256 threads) ----
    __shared__ float tkn[G_D];
    __shared__ float cn[M_CL];
    __shared__ float red[8];
    const int lane = tid & 31, wid = tid >> 5;
    const float* aggb = g_AGG + (size_t)b * L_D * M_CL;

    float tv = g_TK[(size_t)b * G_D + tid];
    {
        float val = tv * tv;
        #pragma unroll
        for (int off = 16; off; off >>= 1) val += __shfl_xor_sync(0xFFFFFFFFu, val, off);
        if (lane == 0) red[wid] = val;
        __syncthreads();
        float s = red[0] + red[1] + red[2] + red[3] + red[4] + red[5] + red[6] + red[7];
        tkn[tid] = tv / fmaxf(sqrtf(s), EPSV);
    }
    __syncthreads();

    if (tid < M_CL) {
        float s = 0.f;
        for (int l = 0; l < L_D; ++l) {
            float a = aggb[(size_t)l * M_CL + tid];
            s = fmaf(a, a, s);
        }
        cn[tid] = fmaxf(sqrtf(s), EPSV);
    }
    __syncthreads();

    float gs = tkn[tid] * tkn[tid];
    for (int idx = tid; idx < L_D * M_CL; idx += 256) {
        float a = aggb[idx] / cn[idx & (M_CL - 1)];
        gs = fmaf(a, a, gs);
    }
    {
        #pragma unroll
        for (int off = 16; off; off >>= 1) gs += __shfl_xor_sync(0xFFFFFFFFu, gs, off);
        if (lane == 0) red[wid] = gs;
        __syncthreads();
        float total = red[0] + red[1] + red[2] + red[3] + red[4] + red[5] + red[6] + red[7];
        float scale = 1.f / fmaxf(sqrtf(total), EPSV);

        float* ob = out + (size_t)b * (G_D + L_D * M_CL);
        ob[tid] = tkn[tid] * scale;
        for (int idx = tid; idx < L_D * M_CL; idx += 256)
            ob[G_D + idx] = (aggb[idx] / cn[idx & (M_CL - 1)]) * scale;
    }

    // reset counter for the next graph replay (deterministic)
    __syncthreads();
    if (tid == 0) g_cnt[b] = 0;
}

// ---------------------------------------------------------------------------
// Launch: main chain + one side stream (weights + token MLP)
// ---------------------------------------------------------------------------
extern "C" void kernel_launch(void* const* d_in, const int* in_sizes, int n_in,
                              void* d_out, int out_size)
{
    const float* x      = (const float*)d_in[0];
    const float* t      = (const float*)d_in[1];
    const float* cf_w1  = (const float*)d_in[2];
    const float* cf_b1  = (const float*)d_in[3];
    const float* cf_w2  = (const float*)d_in[4];
    const float* cf_b2  = (const float*)d_in[5];
    const float* sc_w1  = (const float*)d_in[6];
    const float* sc_b1  = (const float*)d_in[7];
    const float* sc_w2  = (const float*)d_in[8];
    const float* sc_b2  = (const float*)d_in[9];
    const float* tk_w1  = (const float*)d_in[10];
    const float* tk_b1  = (const float*)d_in[11];
    const float* tk_w2  = (const float*)d_in[12];
    const float* tk_b2  = (const float*)d_in[13];
    const float* dust   = (const float*)d_in[14];

    float *F, *Z, *B1, *B2;
    __half *X, *W1, *W2, *H;
    cudaGetSymbolAddress((void**)&F,  g_F);
    cudaGetSymbolAddress((void**)&Z,  g_Z);
    cudaGetSymbolAddress((void**)&B1, g_B1c);
    cudaGetSymbolAddress((void**)&B2, g_B2c);
    cudaGetSymbolAddress((void**)&X,  g_X);
    cudaGetSymbolAddress((void**)&W1, g_W1);
    cudaGetSymbolAddress((void**)&W2, g_W2);
    cudaGetSymbolAddress((void**)&H,  g_H);

    static cudaStream_t s_side = nullptr;
    static cudaEvent_t ev_fork = nullptr, ev_w = nullptr, ev_tok = nullptr;
    if (!s_side) {
        cudaStreamCreateWithFlags(&s_side, cudaStreamNonBlocking);
        cudaEventCreateWithFlags(&ev_fork, cudaEventDisableTiming);
        cudaEventCreateWithFlags(&ev_w,    cudaEventDisableTiming);
        cudaEventCreateWithFlags(&ev_tok,  cudaEventDisableTiming);
        cudaFuncSetAttribute(mma_gemm1_kernel,
                             cudaFuncAttributeMaxDynamicSharedMemorySize, GEMM_SMEM);
        cudaFuncSetAttribute(mma_gemm2_kernel,
                             cudaFuncAttributeMaxDynamicSharedMemorySize, GEMM_SMEM);
    }

    // fork
    cudaEventRecord(ev_fork, 0);
    cudaStreamWaitEvent(s_side, ev_fork, 0);

    // side stream: merged weight conversion, then token MLP
    convert_all_kernel<<<(1024 * C_SZ + 255) / 256, 256, 0, s_side>>>(
        cf_w1, sc_w1, cf_b1, sc_b1, cf_w2, sc_w2, cf_b2, sc_b2);
    cudaEventRecord(ev_w, s_side);
    token_kernel<<<B_SZ, 256, 0, s_side>>>(t, tk_w1, tk_b1, tk_w2, tk_b2);
    cudaEventRecord(ev_tok, s_side);

    // main chain
    convert_x_kernel<<<(int)(((size_t)B_SZ * C_SZ * HW / 8 + 255) / 256), 256>>>(
        (const float4*)x);
    cudaStreamWaitEvent(0, ev_w, 0);
    mma_gemm1_kernel<<<dim3(HW / NT, 1024 / MT, B_SZ), 256, GEMM_SMEM>>>(
        W1, X, B1, H);
    mma_gemm2_kernel<<<dim3(HW / NT, 2, B_SZ), 256, GEMM_SMEM>>>(
        W2, H, B2, F, Z);
    sinkhorn_kernel<<<B_SZ, 512>>>(dust);
    cudaStreamWaitEvent(0, ev_tok, 0);   // g_TK needed by fused finalize
    agg_finalize_kernel<<<dim3(4, B_SZ), 256>>>((float*)d_out);
}

// round 17
// speedup vs baseline: 1.0783x; 1.0783x over previous
#include <cuda_runtime.h>
#include <cuda_fp16.h>
#include <math.h>
#include <stdint.h>

// ---------------------------------------------------------------------------
// SALAD pipeline. Final (= Round 11, best measured 421.4 us):
//   - gemm1/gemm2: fp16 single-product HMMA, CTA 128x128, KC=64, 3-stage
//     cp.async, 2 CTAs/SM (converged local optimum; 5 profiles at 237 us/72%)
//   - merged weight convert + fused token MLP on one side stream
//   - sinkhorn (512 thr), agg (128 blocks), finalize (32 blocks)
// ---------------------------------------------------------------------------

#define B_SZ 32
#define C_SZ 1536
#define HW   1024
#define HID  512
#define L_D  128
#define M_CL 64
#define G_D  256
#define EPSV 1e-12f

__device__ __align__(256) __half g_H[(size_t)B_SZ * 1024 * HW];      // H [b][k][n]
__device__ __align__(256) float g_F[(size_t)B_SZ * L_D * HW];
__device__ __align__(256) float g_Z[(size_t)B_SZ * (M_CL + 1) * HW];
__device__ __align__(256) float g_AGG[(size_t)B_SZ * L_D * M_CL];
__device__ __align__(256) float g_TK[(size_t)B_SZ * G_D];

__device__ __align__(256) __half g_X[(size_t)B_SZ * C_SZ * HW];  // x [b][c][n]
__device__ __align__(256) __half g_W1[(size_t)1024 * C_SZ];      // [cf_w1; sc_w1]
__device__ __align__(256) __half g_W2[(size_t)256 * HID];        // [cf_w2; sc_w2; 0]
__device__ __align__(256) float g_B1c[1024];
__device__ __align__(256) float g_B2c[256];

// ---------------------------------------------------------------------------
__device__ __forceinline__ uint32_t smem_u32(const void* p) {
    uint32_t a;
    asm("{ .reg .u64 t; cvta.to.shared.u64 t, %1; cvt.u32.u64 %0, t; }"
        : "=r"(a) : "l"(p));
    return a;
}

__device__ __forceinline__ void cp16(uint32_t saddr, const void* gaddr) {
    asm volatile("cp.async.cg.shared.global [%0], [%1], 16;"
                 :: "r"(saddr), "l"(gaddr) : "memory");
}

#define LDSM_X4(r0, r1, r2, r3, addr) \
    asm volatile("ldmatrix.sync.aligned.m8n8.x4.shared.b16 {%0,%1,%2,%3}, [%4];" \
                 : "=r"(r0), "=r"(r1), "=r"(r2), "=r"(r3) : "r"(addr))

#define LDSM_X4_T(r0, r1, r2, r3, addr) \
    asm volatile("ldmatrix.sync.aligned.m8n8.x4.trans.shared.b16 {%0,%1,%2,%3}, [%4];" \
                 : "=r"(r0), "=r"(r1), "=r"(r2), "=r"(r3) : "r"(addr))

#define MMA_F16(d, a, b0, b1) \
    asm volatile("mma.sync.aligned.m16n8k16.row.col.f32.f16.f16.f32 " \
                 "{%0,%1,%2,%3}, {%4,%5,%6,%7}, {%8,%9}, {%0,%1,%2,%3};" \
                 : "+f"((d)[0]), "+f"((d)[1]), "+f"((d)[2]), "+f"((d)[3]) \
                 : "r"((a)[0]), "r"((a)[1]), "r"((a)[2]), "r"((a)[3]), \
                   "r"(b0), "r"(b1))

// ---------------------------------------------------------------------------
// Merged weight conversion
// ---------------------------------------------------------------------------
__global__ __launch_bounds__(256)
void convert_all_kernel(const float* __restrict__ cf_w1, const float* __restrict__ sc_w1,
                        const float* __restrict__ cf_b1, const float* __restrict__ sc_b1,
                        const float* __restrict__ cf_w2, const float* __restrict__ sc_w2,
                        const float* __restrict__ cf_b2, const float* __restrict__ sc_b2)
{
    size_t idx = (size_t)blockIdx.x * 256 + threadIdx.x;
    const size_t totalW1 = (size_t)1024 * C_SZ;
    if (idx < totalW1) {
        float v = (idx < (size_t)HID * C_SZ) ? cf_w1[idx]
                                             : sc_w1[idx - (size_t)HID * C_SZ];
        g_W1[idx] = __float2half_rn(v);
    }
    if (idx < (size_t)256 * HID) {
        size_t row = idx / HID;
        float v = 0.f;
        if (row < L_D)      v = cf_w2[idx];
        else if (row < 192) v = sc_w2[idx - (size_t)L_D * HID];
        g_W2[idx] = __float2half_rn(v);
    }
    if (idx < 1024)
        g_B1c[idx] = (idx < HID) ? cf_b1[idx] : sc_b1[idx - HID];
    if (idx < 256)
        g_B2c[idx] = (idx < L_D) ? cf_b2[idx]
                   : (idx < 192) ? sc_b2[idx - L_D] : 0.f;
}

__global__ __launch_bounds__(256)
void convert_x_kernel(const float4* __restrict__ x)
{
    const size_t i = (size_t)blockIdx.x * 256 + threadIdx.x;
    float4 a = x[2 * i];
    float4 b = x[2 * i + 1];
    __half2 h0 = __floats2half2_rn(a.x, a.y);
    __half2 h1 = __floats2half2_rn(a.z, a.w);
    __half2 h2 = __floats2half2_rn(b.x, b.y);
    __half2 h3 = __floats2half2_rn(b.z, b.w);
    uint4 o;
    o.x = *reinterpret_cast<uint32_t*>(&h0);
    o.y = *reinterpret_cast<uint32_t*>(&h1);
    o.z = *reinterpret_cast<uint32_t*>(&h2);
    o.w = *reinterpret_cast<uint32_t*>(&h3);
    reinterpret_cast<uint4*>(g_X)[i] = o;
}

// ---------------------------------------------------------------------------
// GEMM1 (fp16 HMMA): H[b] = relu(W1 @ X[b] + b1) -> fp16
//   CTA 128x128, KC=64, 3-stage cp.async, 2 CTAs/SM.
// ---------------------------------------------------------------------------
#define MT 128
#define NT 128
#define KC 64
#define NK1 (C_SZ / KC)               // 24
#define NK2 (HID / KC)                // 8
#define OFF_A 0
#define OFF_B (16 * 1024)
#define STAGE_BYTES (32 * 1024)
#define GEMM_SMEM (3 * STAGE_BYTES)   // 96 KB

__global__ __launch_bounds__(256, 2)
void mma_gemm1_kernel(const __half* __restrict__ W1, const __half* __restrict__ X,
                      const float* __restrict__ bias, __half* __restrict__ H)
{
    extern __shared__ char dsmem[];
    const uint32_t smem_base = smem_u32(dsmem);

    const int tid = threadIdx.x;
    const int b  = blockIdx.z;
    const int n0 = blockIdx.x * NT;
    const int m0 = blockIdx.y * MT;

    const __half* Ag = W1 + (size_t)m0 * C_SZ;
    const __half* Bg = X + (size_t)b * C_SZ * HW + n0;

    const int lane = tid & 31, warp = tid >> 5;
    const int wm = warp >> 2, wn = warp & 3;

    const uint32_t lx = (uint32_t)(lane & 7);
    const uint32_t aG = (uint32_t)(lane >> 4);
    const uint32_t aRowOff = (uint32_t)(wm * 64 + (lane & 15)) * 128u;
    const uint32_t bRowOff = (uint32_t)(lane & 15) * 256u;
    const uint32_t bGbase = (uint32_t)(wn * 4) + (uint32_t)(lane >> 4);

    float acc[4][4][4];
    #pragma unroll
    for (int i = 0; i < 4; ++i)
        #pragma unroll
        for (int j = 0; j < 4; ++j)
            #pragma unroll
            for (int q = 0; q < 4; ++q) acc[i][j][q] = 0.f;

    auto load_chunk = [&](int c) {
        const uint32_t sb = smem_base + (uint32_t)(c % 3) * STAGE_BYTES;
        const size_t kk = (size_t)c * KC;
        #pragma unroll
        for (int i = 0; i < 4; ++i) {
            int idx = tid + 256 * i;
            int r = idx >> 3, g = idx & 7;
            uint32_t so = (uint32_t)r * 128u + (uint32_t)((g ^ (r & 7)) << 4);
            cp16(sb + OFF_A + so, (const char*)(Ag + (size_t)r * C_SZ + kk) + g * 16);
        }
        #pragma unroll
        for (int i = 0; i < 4; ++i) {
            int idx = tid + 256 * i;
            int r = idx >> 4, g = idx & 15;
            uint32_t so = (uint32_t)r * 256u + (uint32_t)((g ^ (r & 7)) << 4);
            cp16(sb + OFF_B + so, (const char*)(Bg + (kk + r) * HW) + g * 16);
        }
        asm volatile("cp.async.commit_group;" ::: "memory");
    };

    load_chunk(0);
    load_chunk(1);

    for (int c = 0; c < NK1; ++c) {
        if (c + 2 < NK1) {
            load_chunk(c + 2);
            asm volatile("cp.async.wait_group 2;" ::: "memory");
        } else if (c + 1 < NK1) {
            asm volatile("cp.async.wait_group 1;" ::: "memory");
        } else {
            asm volatile("cp.async.wait_group 0;" ::: "memory");
        }
        __syncthreads();

        const uint32_t sb = smem_base + (uint32_t)(c % 3) * STAGE_BYTES;

        #pragma unroll
        for (int ks = 0; ks < 4; ++ks) {
            const uint32_t gA = ((uint32_t)(ks * 2) + aG) ^ lx;
            const uint32_t bRow = (uint32_t)(ks * 16) * 256u + bRowOff;

            uint32_t ah[16], bh[8];
            #pragma unroll
            for (int ma = 0; ma < 4; ++ma) {
                uint32_t ad = sb + OFF_A + aRowOff + (uint32_t)(ma * 16 * 128) + (gA << 4);
                LDSM_X4(ah[4*ma+0], ah[4*ma+1], ah[4*ma+2], ah[4*ma+3], ad);
            }
            #pragma unroll
            for (int nb = 0; nb < 2; ++nb) {
                uint32_t gB = (bGbase + (uint32_t)(nb * 2)) ^ lx;
                uint32_t bd = sb + OFF_B + bRow + (gB << 4);
                LDSM_X4_T(bh[4*nb+0], bh[4*nb+1], bh[4*nb+2], bh[4*nb+3], bd);
            }
            #pragma unroll
            for (int ma = 0; ma < 4; ++ma)
                #pragma unroll
                for (int na = 0; na < 4; ++na)
                    MMA_F16(acc[ma][na], &ah[4*ma], bh[2*na], bh[2*na+1]);
        }
        __syncthreads();
    }

    const int g  = lane >> 2;
    const int tc = lane & 3;
    #pragma unroll
    for (int ma = 0; ma < 4; ++ma) {
        const int r0 = m0 + wm * 64 + ma * 16 + g;
        const int r1 = r0 + 8;
        const float bb0 = bias[r0];
        const float bb1 = bias[r1];
        const size_t base0 = ((size_t)b * 1024 + r0) * HW + n0 + wn * 32 + tc * 2;
        const size_t base1 = ((size_t)b * 1024 + r1) * HW + n0 + wn * 32 + tc * 2;
        #pragma unroll
        for (int na = 0; na < 4; ++na) {
            float v00 = fmaxf(acc[ma][na][0] + bb0, 0.f);
            float v01 = fmaxf(acc[ma][na][1] + bb0, 0.f);
            float v10 = fmaxf(acc[ma][na][2] + bb1, 0.f);
            float v11 = fmaxf(acc[ma][na][3] + bb1, 0.f);
            *reinterpret_cast<__half2*>(H + base0 + na * 8) = __floats2half2_rn(v00, v01);
            *reinterpret_cast<__half2*>(H + base1 + na * 8) = __floats2half2_rn(v10, v11);
        }
    }
}

// ---------------------------------------------------------------------------
// GEMM2 (fp16 HMMA, gemm1 clone): [F; Z] = W2p @ H + b2p
// ---------------------------------------------------------------------------
__global__ __launch_bounds__(256, 2)
void mma_gemm2_kernel(const __half* __restrict__ W2p, const __half* __restrict__ H,
                      const float* __restrict__ bias,
                      float* __restrict__ Fout, float* __restrict__ Zout)
{
    extern __shared__ char dsmem[];
    const uint32_t smem_base = smem_u32(dsmem);

    const int tid = threadIdx.x;
    const int b  = blockIdx.z;
    const int n0 = blockIdx.x * NT;
    const int m0 = blockIdx.y * MT;                // 0 or 128
    const int koff = (m0 == 128) ? 512 : 0;

    const __half* Ag = W2p + (size_t)m0 * HID;
    const __half* Bg = H + ((size_t)b * 1024 + koff) * HW + n0;

    const int lane = tid & 31, warp = tid >> 5;
    const int wm = warp >> 2, wn = warp & 3;

    const uint32_t lx = (uint32_t)(lane & 7);
    const uint32_t aG = (uint32_t)(lane >> 4);
    const uint32_t aRowOff = (uint32_t)(wm * 64 + (lane & 15)) * 128u;
    const uint32_t bRowOff = (uint32_t)(lane & 15) * 256u;
    const uint32_t bGbase = (uint32_t)(wn * 4) + (uint32_t)(lane >> 4);

    float acc[4][4][4];
    #pragma unroll
    for (int i = 0; i < 4; ++i)
        #pragma unroll
        for (int j = 0; j < 4; ++j)
            #pragma unroll
            for (int q = 0; q < 4; ++q) acc[i][j][q] = 0.f;

    auto load_chunk = [&](int c) {
        const uint32_t sb = smem_base + (uint32_t)(c % 3) * STAGE_BYTES;
        const size_t kk = (size_t)c * KC;
        #pragma unroll
        for (int i = 0; i < 4; ++i) {
            int idx = tid + 256 * i;
            int r = idx >> 3, g = idx & 7;
            uint32_t so = (uint32_t)r * 128u + (uint32_t)((g ^ (r & 7)) << 4);
            cp16(sb + OFF_A + so, (const char*)(Ag + (size_t)r * HID + kk) + g * 16);
        }
        #pragma unroll
        for (int i = 0; i < 4; ++i) {
            int idx = tid + 256 * i;
            int r = idx >> 4, g = idx & 15;
            uint32_t so = (uint32_t)r * 256u + (uint32_t)((g ^ (r & 7)) << 4);
            cp16(sb + OFF_B + so, (const char*)(Bg + (kk + r) * HW) + g * 16);
        }
        asm volatile("cp.async.commit_group;" ::: "memory");
    };

    load_chunk(0);
    load_chunk(1);

    for (int c = 0; c < NK2; ++c) {
        if (c + 2 < NK2) {
            load_chunk(c + 2);
            asm volatile("cp.async.wait_group 2;" ::: "memory");
        } else if (c + 1 < NK2) {
            asm volatile("cp.async.wait_group 1;" ::: "memory");
        } else {
            asm volatile("cp.async.wait_group 0;" ::: "memory");
        }
        __syncthreads();

        const uint32_t sb = smem_base + (uint32_t)(c % 3) * STAGE_BYTES;

        #pragma unroll
        for (int ks = 0; ks < 4; ++ks) {
            const uint32_t gA = ((uint32_t)(ks * 2) + aG) ^ lx;
            const uint32_t bRow = (uint32_t)(ks * 16) * 256u + bRowOff;

            uint32_t ah[16], bh[8];
            #pragma unroll
            for (int ma = 0; ma < 4; ++ma) {
                uint32_t ad = sb + OFF_A + aRowOff + (uint32_t)(ma * 16 * 128) + (gA << 4);
                LDSM_X4(ah[4*ma+0], ah[4*ma+1], ah[4*ma+2], ah[4*ma+3], ad);
            }
            #pragma unroll
            for (int nb = 0; nb < 2; ++nb) {
                uint32_t gB = (bGbase + (uint32_t)(nb * 2)) ^ lx;
                uint32_t bd = sb + OFF_B + bRow + (gB << 4);
                LDSM_X4_T(bh[4*nb+0], bh[4*nb+1], bh[4*nb+2], bh[4*nb+3], bd);
            }
            #pragma unroll
            for (int ma = 0; ma < 4; ++ma)
                #pragma unroll
                for (int na = 0; na < 4; ++na)
                    MMA_F16(acc[ma][na], &ah[4*ma], bh[2*na], bh[2*na+1]);
        }
        __syncthreads();
    }

    const int g  = lane >> 2;
    const int tc = lane & 3;
    #pragma unroll
    for (int ma = 0; ma < 4; ++ma) {
        const int r0 = m0 + wm * 64 + ma * 16 + g;
        const int r1 = r0 + 8;
        const float bb0 = bias[r0];
        const float bb1 = bias[r1];
        float* p0 = nullptr;
        float* p1 = nullptr;
        if (r0 < L_D)      p0 = Fout + ((size_t)b * L_D + r0) * HW;
        else if (r0 < 192) p0 = Zout + ((size_t)b * (M_CL + 1) + (r0 - L_D)) * HW;
        if (r1 < L_D)      p1 = Fout + ((size_t)b * L_D + r1) * HW;
        else if (r1 < 192) p1 = Zout + ((size_t)b * (M_CL + 1) + (r1 - L_D)) * HW;
        const int coff = n0 + wn * 32 + tc * 2;
        #pragma unroll
        for (int na = 0; na < 4; ++na) {
            if (p0) {
                float2 v0;
                v0.x = acc[ma][na][0] + bb0;
                v0.y = acc[ma][na][1] + bb0;
                *reinterpret_cast<float2*>(p0 + coff + na * 8) = v0;
            }
            if (p1) {
                float2 v1;
                v1.x = acc[ma][na][2] + bb1;
                v1.y = acc[ma][na][3] + bb1;
                *reinterpret_cast<float2*>(p1 + coff + na * 8) = v1;
            }
        }
    }
}

// ---------------------------------------------------------------------------
// Fused token MLP
// ---------------------------------------------------------------------------
__global__ __launch_bounds__(256)
void token_kernel(const float* __restrict__ t,
                  const float* __restrict__ w1, const float* __restrict__ b1,
                  const float* __restrict__ w2, const float* __restrict__ b2)
{
    __shared__ float ts[C_SZ];
    __shared__ float hs[HID];
    const int b = blockIdx.x;
    for (int c = threadIdx.x; c < C_SZ; c += 256) ts[c] = t[(size_t)b * C_SZ + c];
    __syncthreads();
    const int wid = threadIdx.x >> 5, lane = threadIdx.x & 31;
    for (int o = wid; o < HID; o += 8) {
        const float* wr = w1 + (size_t)o * C_SZ;
        float s = 0.f;
        for (int c = lane; c < C_SZ; c += 32) s = fmaf(ts[c], wr[c], s);
        #pragma unroll
        for (int off = 16; off; off >>= 1) s += __shfl_xor_sync(0xFFFFFFFFu, s, off);
        if (lane == 0) hs[o] = fmaxf(s + b1[o], 0.f);
    }
    __syncthreads();
    for (int o = wid; o < G_D; o += 8) {
        const float* wr = w2 + (size_t)o * HID;
        float s = 0.f;
        for (int c = lane; c < HID; c += 32) s = fmaf(hs[c], wr[c], s);
        #pragma unroll
        for (int off = 16; off; off >>= 1) s += __shfl_xor_sync(0xFFFFFFFFu, s, off);
        if (lane == 0) g_TK[(size_t)b * G_D + o] = s + b2[o];
    }
}

// ---------------------------------------------------------------------------
// Sinkhorn, 512 threads (2 columns/thread), one block per batch.
// Overwrites Z rows 0..63 with P in place.
// ---------------------------------------------------------------------------
__global__ __launch_bounds__(512)
void sinkhorn_kernel(const float* __restrict__ alpha_p)
{
    const int b = blockIdx.x;
    float* Zb = g_Z + (size_t)b * (M_CL + 1) * HW;

    __shared__ float u[M_CL + 1];
    __shared__ float wsum[M_CL + 1][17];

    const int j = threadIdx.x;
    const int lane = j & 31, warp = j >> 5;   // 16 warps
    const float alpha = *alpha_p;
    const float norm = -logf((float)(M_CL + HW));
    const float log_mu_last = logf((float)(HW - M_CL)) + norm;

    float v0 = 0.f, v1 = 0.f;

    for (int it = 0; it < 3; ++it) {
        #pragma unroll 4
        for (int i = 0; i <= M_CL; ++i) {
            float z0, z1;
            if (i < M_CL) {
                z0 = Zb[(size_t)i * HW + j] + v0;
                z1 = Zb[(size_t)i * HW + j + 512] + v1;
            } else {
                z0 = alpha + v0;
                z1 = alpha + v1;
            }
            float e = __expf(z0) + __expf(z1);
            #pragma unroll
            for (int off = 16; off; off >>= 1) e += __shfl_xor_sync(0xFFFFFFFFu, e, off);
            if (lane == 0) wsum[i][warp] = e;
        }
        __syncthreads();
        if (j <= M_CL) {
            float s = 0.f;
            #pragma unroll
            for (int w = 0; w < 16; ++w) s += wsum[j][w];
            u[j] = ((j < M_CL) ? norm : log_mu_last) - logf(s);
        }
        __syncthreads();

        float s0 = 0.f, s1 = 0.f;
        #pragma unroll 8
        for (int i = 0; i < M_CL; ++i) {
            s0 += __expf(Zb[(size_t)i * HW + j] + u[i]);
            s1 += __expf(Zb[(size_t)i * HW + j + 512] + u[i]);
        }
        s0 += __expf(alpha + u[M_CL]);
        s1 += __expf(alpha + u[M_CL]);
        v0 = norm - logf(s0);
        v1 = norm - logf(s1);
    }

    #pragma unroll 8
    for (int i = 0; i < M_CL; ++i) {
        Zb[(size_t)i * HW + j]       = __expf(Zb[(size_t)i * HW + j] + u[i] + v0 - norm);
        Zb[(size_t)i * HW + j + 512] = __expf(Zb[(size_t)i * HW + j + 512] + u[i] + v1 - norm);
    }
}

// ---------------------------------------------------------------------------
// agg[b][l][m] = sum_n F[b][l][n] * P[b][m][n]; grid (4 l-quads, B)
// ---------------------------------------------------------------------------
__global__ __launch_bounds__(256)
void agg_kernel()
{
    const int b = blockIdx.y;
    const int l0 = blockIdx.x * 32;
    const float* Fb = g_F + (size_t)b * L_D * HW + (size_t)l0 * HW;
    const float* Pb = g_Z + (size_t)b * (M_CL + 1) * HW;
    float*       Cb = g_AGG + (size_t)b * L_D * M_CL + (size_t)l0 * M_CL;

    __shared__ float Fs[32][36];
    __shared__ float Ps[32][68];

    const int tid = threadIdx.x;
    const int tx = tid & 15, ty = tid >> 4;

    float acc[2][4];
    #pragma unroll
    for (int i = 0; i < 2; ++i)
        #pragma unroll
        for (int j = 0; j < 4; ++j) acc[i][j] = 0.f;

    for (int n0 = 0; n0 < HW; n0 += 32) {
        {
            int l = tid >> 3, kq = (tid & 7) << 2;
            float4 fv = *reinterpret_cast<const float4*>(&Fb[(size_t)l * HW + n0 + kq]);
            Fs[kq + 0][l] = fv.x; Fs[kq + 1][l] = fv.y;
            Fs[kq + 2][l] = fv.z; Fs[kq + 3][l] = fv.w;
        }
        #pragma unroll
        for (int r = 0; r < 2; ++r) {
            int id = tid + 256 * r;
            int m = id >> 3, kq = (id & 7) << 2;
            float4 pv = *reinterpret_cast<const float4*>(&Pb[(size_t)m * HW + n0 + kq]);
            Ps[kq + 0][m] = pv.x; Ps[kq + 1][m] = pv.y;
            Ps[kq + 2][m] = pv.z; Ps[kq + 3][m] = pv.w;
        }
        __syncthreads();

        #pragma unroll
        for (int k = 0; k < 32; ++k) {
            float rl[2], rm[4];
            #pragma unroll
            for (int i = 0; i < 2; ++i) rl[i] = Fs[k][ty * 2 + i];
            #pragma unroll
            for (int j = 0; j < 4; ++j) rm[j] = Ps[k][tx * 4 + j];
            #pragma unroll
            for (int i = 0; i < 2; ++i)
                #pragma unroll
                for (int j = 0; j < 4; ++j)
                    acc[i][j] = fmaf(rl[i], rm[j], acc[i][j]);
        }
        __syncthreads();
    }

    #pragma unroll
    for (int i = 0; i < 2; ++i)
        #pragma unroll
        for (int j = 0; j < 4; ++j)
            Cb[(size_t)(ty * 2 + i) * M_CL + tx * 4 + j] = acc[i][j];
}

// ---------------------------------------------------------------------------
// Finalize
// ---------------------------------------------------------------------------
__device__ __forceinline__ float block_sum256(float val, float* red)
{
    const int lane = threadIdx.x & 31, wid = threadIdx.x >> 5;
    #pragma unroll
    for (int off = 16; off; off >>= 1) val += __shfl_xor_sync(0xFFFFFFFFu, val, off);
    if (lane == 0) red[wid] = val;
    __syncthreads();
    float s = red[0] + red[1] + red[2] + red[3] + red[4] + red[5] + red[6] + red[7];
    __syncthreads();
    return s;
}

__global__ __launch_bounds__(256)
void finalize_kernel(float* __restrict__ out)
{
    const int b = blockIdx.x;
    const int tid = threadIdx.x;
    __shared__ float tkn[G_D];
    __shared__ float cn[M_CL];
    __shared__ float red[8];

    const float* aggb = g_AGG + (size_t)b * L_D * M_CL;

    float tv = g_TK[(size_t)b * G_D + tid];
    float tk_ss = block_sum256(tv * tv, red);
    tkn[tid] = tv / fmaxf(sqrtf(tk_ss), EPSV);

    if (tid < M_CL) {
        float s = 0.f;
        for (int l = 0; l < L_D; ++l) {
            float a = aggb[(size_t)l * M_CL + tid];
            s = fmaf(a, a, s);
        }
        cn[tid] = fmaxf(sqrtf(s), EPSV);
    }
    __syncthreads();

    float gs = tkn[tid] * tkn[tid];
    for (int idx = tid; idx < L_D * M_CL; idx += 256) {
        float a = aggb[idx] / cn[idx & (M_CL - 1)];
        gs = fmaf(a, a, gs);
    }
    float total = block_sum256(gs, red);
    float scale = 1.f / fmaxf(sqrtf(total), EPSV);

    float* ob = out + (size_t)b * (G_D + L_D * M_CL);
    ob[tid] = tkn[tid] * scale;
    for (int idx = tid; idx < L_D * M_CL; idx += 256)
        ob[G_D + idx] = (aggb[idx] / cn[idx & (M_CL - 1)]) * scale;
}

// ---------------------------------------------------------------------------
// Launch: main chain + one side stream (weights + token MLP)
// ---------------------------------------------------------------------------
extern "C" void kernel_launch(void* const* d_in, const int* in_sizes, int n_in,
                              void* d_out, int out_size)
{
    const float* x      = (const float*)d_in[0];
    const float* t      = (const float*)d_in[1];
    const float* cf_w1  = (const float*)d_in[2];
    const float* cf_b1  = (const float*)d_in[3];
    const float* cf_w2  = (const float*)d_in[4];
    const float* cf_b2  = (const float*)d_in[5];
    const float* sc_w1  = (const float*)d_in[6];
    const float* sc_b1  = (const float*)d_in[7];
    const float* sc_w2  = (const float*)d_in[8];
    const float* sc_b2  = (const float*)d_in[9];
    const float* tk_w1  = (const float*)d_in[10];
    const float* tk_b1  = (const float*)d_in[11];
    const float* tk_w2  = (const float*)d_in[12];
    const float* tk_b2  = (const float*)d_in[13];
    const float* dust   = (const float*)d_in[14];

    float *F, *Z, *B1, *B2;
    __half *X, *W1, *W2, *H;
    cudaGetSymbolAddress((void**)&F,  g_F);
    cudaGetSymbolAddress((void**)&Z,  g_Z);
    cudaGetSymbolAddress((void**)&B1, g_B1c);
    cudaGetSymbolAddress((void**)&B2, g_B2c);
    cudaGetSymbolAddress((void**)&X,  g_X);
    cudaGetSymbolAddress((void**)&W1, g_W1);
    cudaGetSymbolAddress((void**)&W2, g_W2);
    cudaGetSymbolAddress((void**)&H,  g_H);

    static cudaStream_t s_side = nullptr;
    static cudaEvent_t ev_fork = nullptr, ev_w = nullptr, ev_tok = nullptr;
    if (!s_side) {
        cudaStreamCreateWithFlags(&s_side, cudaStreamNonBlocking);
        cudaEventCreateWithFlags(&ev_fork, cudaEventDisableTiming);
        cudaEventCreateWithFlags(&ev_w,    cudaEventDisableTiming);
        cudaEventCreateWithFlags(&ev_tok,  cudaEventDisableTiming);
        cudaFuncSetAttribute(mma_gemm1_kernel,
                             cudaFuncAttributeMaxDynamicSharedMemorySize, GEMM_SMEM);
        cudaFuncSetAttribute(mma_gemm2_kernel,
                             cudaFuncAttributeMaxDynamicSharedMemorySize, GEMM_SMEM);
    }

    // fork
    cudaEventRecord(ev_fork, 0);
    cudaStreamWaitEvent(s_side, ev_fork, 0);

    // side stream: merged weight conversion, then token MLP
    convert_all_kernel<<<(1024 * C_SZ + 255) / 256, 256, 0, s_side>>>(
        cf_w1, sc_w1, cf_b1, sc_b1, cf_w2, sc_w2, cf_b2, sc_b2);
    cudaEventRecord(ev_w, s_side);
    token_kernel<<<B_SZ, 256, 0, s_side>>>(t, tk_w1, tk_b1, tk_w2, tk_b2);
    cudaEventRecord(ev_tok, s_side);

    // main chain
    convert_x_kernel<<<(int)(((size_t)B_SZ * C_SZ * HW / 8 + 255) / 256), 256>>>(
        (const float4*)x);
    cudaStreamWaitEvent(0, ev_w, 0);
    mma_gemm1_kernel<<<dim3(HW / NT, 1024 / MT, B_SZ), 256, GEMM_SMEM>>>(
        W1, X, B1, H);
    mma_gemm2_kernel<<<dim3(HW / NT, 2, B_SZ), 256, GEMM_SMEM>>>(
        W2, H, B2, F, Z);
    sinkhorn_kernel<<<B_SZ, 512>>>(dust);
    agg_kernel<<<dim3(4, B_SZ), 256>>>();
    cudaStreamWaitEvent(0, ev_tok, 0);
    finalize_kernel<<<B_SZ, 256>>>((float*)d_out);
}